// round 14
// baseline (speedup 1.0000x reference)
#include <cuda_runtime.h>
#include <cuda_fp16.h>
#include <cstdint>

// ---------------------------------------------------------------------------
// Shifted-window MSA. B=8, NSEQ=16384, C=256, P=64, SHIFT=32, NH=8, HD=32.
//   K0: cvt x(rolled)->fp16, w_qkv->fp16, w_out->fp16
//   K1: QKV GEMM (fp16 mma, 128x128 block, cp.async 3-stage) -> g_qkv (fp16)
//   K2: attention (fp16 mma, per window-head)                -> g_att (fp16)
//   K3: out GEMM (same, roll on write)                       -> d_out (fp32)
// tcgen05 unusable: harness ptxas targets sm_103 (no 'a' features).
// ---------------------------------------------------------------------------

#define BATCH   8
#define NSEQ    16384
#define CDIM    256
#define PWIN    64
#define SHIFT   32
#define NHEADS  8
#define HDIM    32
#define MTOT    (BATCH * NSEQ)
#define QKV_N   768
#define NWIN    (MTOT / PWIN)
#define WPB     (NSEQ / PWIN)

__device__ __half g_qkv [(size_t)MTOT * QKV_N];
__device__ __half g_att [(size_t)MTOT * CDIM];
__device__ __half g_xh  [(size_t)MTOT * CDIM];
__device__ __half g_wqkvh[(size_t)QKV_N * CDIM];
__device__ __half g_wouth[(size_t)CDIM * CDIM];

// ---------------------------------------------------------------------------
__device__ __forceinline__ uint32_t smem_u32(const void* p) {
    return (uint32_t)__cvta_generic_to_shared(p);
}
__device__ __forceinline__ void mma_f16(float (&d)[4],
                                        const uint32_t (&a)[4],
                                        const uint32_t (&b)[2]) {
    asm volatile(
        "mma.sync.aligned.m16n8k16.row.col.f32.f16.f16.f32 "
        "{%0,%1,%2,%3}, {%4,%5,%6,%7}, {%8,%9}, {%0,%1,%2,%3};"
        : "+f"(d[0]), "+f"(d[1]), "+f"(d[2]), "+f"(d[3])
        : "r"(a[0]), "r"(a[1]), "r"(a[2]), "r"(a[3]), "r"(b[0]), "r"(b[1]));
}
__device__ __forceinline__ void ldsm_x4(uint32_t (&r)[4], uint32_t addr) {
    asm volatile("ldmatrix.sync.aligned.m8n8.x4.shared.b16 {%0,%1,%2,%3}, [%4];"
        : "=r"(r[0]), "=r"(r[1]), "=r"(r[2]), "=r"(r[3]) : "r"(addr));
}
__device__ __forceinline__ uint32_t h2u(__half2 h) {
    return *reinterpret_cast<uint32_t*>(&h);
}
__device__ __forceinline__ void cp_async16(uint32_t dst, const void* src) {
    asm volatile("cp.async.cg.shared.global [%0], [%1], 16;"
                 :: "r"(dst), "l"(src));
}
#define CP_COMMIT() asm volatile("cp.async.commit_group;" ::: "memory")
#define CP_WAIT(n)  asm volatile("cp.async.wait_group %0;" :: "n"(n) : "memory")

// ---------------------------------------------------------------------------
// FP16 GEMM: C[m,n] = sum_k A[m,k]*W[n,k] + bias[n]
// BM=BN=128, BK=64, 256 threads = 8 warps, warp tile 64x32.
// 3-stage cp.async pipeline, ONE __syncthreads per k-tile:
//   wait(stage kt done) -> barrier -> issue stage kt+2 into freed slot -> MMA.
// Row stride 144B (LDSM conflict-free, 16B aligned).
// Smem: 3 stages x 36KB = 108KB dynamic; 2 CTAs/SM = 216KB <= 228KB.
// ---------------------------------------------------------------------------
#define HBK 64
#define NKT (CDIM / HBK)            // 4
#define ROWB 144                    // row stride bytes
#define STG_B (2 * 128 * ROWB)      // stage stride = 36864 B
#define BOFF (128 * ROWB)           // B matrix offset within stage = 18432 B
#define GSMEM (3 * STG_B)           // 110592 B

template<bool ROLL_OUT, typename OutT>
__global__ void __launch_bounds__(256, 2)
gemm_f16_kernel(const __half* __restrict__ A,
                const __half* __restrict__ W,
                const float* __restrict__ bias,
                OutT* __restrict__ Cout,
                int Ncols)
{
    extern __shared__ __half smem[];
    const uint32_t sbase = smem_u32(smem);

    const int bm = blockIdx.y * 128;
    const int bn = blockIdx.x * 128;

    const int t    = threadIdx.x;
    const int warp = t >> 5;
    const int lane = t & 31;
    const int g    = lane >> 2;
    const int tg   = lane & 3;

    const int wm = (warp & 1) * 64;
    const int wn = (warp >> 1) * 32;

    // gmem->smem map: 128 rows x 8 chunks(16B) per matrix, 4 chunks/thread
    int arow[4], ac[4];
#pragma unroll
    for (int i = 0; i < 4; i++) {
        int id = t + i * 256;
        arow[i] = id >> 3;
        ac[i]   = id & 7;
    }
    const __half* Ab = A + (size_t)bm * CDIM;
    const __half* Wb = W + (size_t)bn * CDIM;

    // per-thread cp.async smem destinations (stage slot 0)
    uint32_t dstA[4];
#pragma unroll
    for (int i = 0; i < 4; i++)
        dstA[i] = sbase + (uint32_t)(arow[i] * ROWB + ac[i] * 16);

    // ldmatrix base addresses (stage slot 0)
    uint32_t aAddr[4], bAddr[2];
#pragma unroll
    for (int mt = 0; mt < 4; mt++)
        aAddr[mt] = sbase + (uint32_t)((wm + mt * 16 + (lane & 15)) * ROWB
                                       + (lane >> 4) * 16);
#pragma unroll
    for (int ntp = 0; ntp < 2; ntp++)
        bAddr[ntp] = sbase + BOFF
                   + (uint32_t)((wn + ntp * 16 + ((lane >> 4) << 3) + (lane & 7)) * ROWB
                                + ((lane >> 3) & 1) * 16);

    float acc[4][4][4];
#pragma unroll
    for (int mt = 0; mt < 4; mt++)
#pragma unroll
        for (int nt = 0; nt < 4; nt++)
#pragma unroll
            for (int r = 0; r < 4; r++) acc[mt][nt][r] = 0.0f;

    // ---- prologue: issue stages 0 and 1 into slots 0 and 1 ----
#pragma unroll
    for (int s = 0; s < 2; s++) {
        const uint32_t so = (uint32_t)(s * STG_B);
        const int k0 = s * HBK;
#pragma unroll
        for (int i = 0; i < 4; i++) {
            cp_async16(dstA[i] + so,        Ab + (size_t)arow[i] * CDIM + k0 + ac[i] * 8);
            cp_async16(dstA[i] + so + BOFF, Wb + (size_t)arow[i] * CDIM + k0 + ac[i] * 8);
        }
        CP_COMMIT();
    }

#pragma unroll 1
    for (int kt = 0; kt < NKT; kt++) {
        if (kt < NKT - 1) CP_WAIT(1);
        else              CP_WAIT(0);
        __syncthreads();   // stage kt ready; all warps done reading slot (kt+2)%3

        // issue stage kt+2 into the slot freed last iteration
        if (kt + 2 < NKT) {
            const uint32_t so2 = (uint32_t)(((kt + 2) % 3) * STG_B);
            const int k0 = (kt + 2) * HBK;
#pragma unroll
            for (int i = 0; i < 4; i++) {
                cp_async16(dstA[i] + so2,        Ab + (size_t)arow[i] * CDIM + k0 + ac[i] * 8);
                cp_async16(dstA[i] + so2 + BOFF, Wb + (size_t)arow[i] * CDIM + k0 + ac[i] * 8);
            }
            CP_COMMIT();
        }

        const uint32_t so = (uint32_t)((kt % 3) * STG_B);
#pragma unroll
        for (int ks = 0; ks < 4; ks++) {
            const uint32_t koff = ks * 32;     // 16 halves
            uint32_t afr[4][4], bp[2][4];
#pragma unroll
            for (int mt = 0; mt < 4; mt++) ldsm_x4(afr[mt], aAddr[mt] + so + koff);
#pragma unroll
            for (int ntp = 0; ntp < 2; ntp++) ldsm_x4(bp[ntp], bAddr[ntp] + so + koff);
#pragma unroll
            for (int mt = 0; mt < 4; mt++)
#pragma unroll
                for (int nt = 0; nt < 4; nt++) {
                    uint32_t bfr[2] = { bp[nt >> 1][(nt & 1) * 2],
                                        bp[nt >> 1][(nt & 1) * 2 + 1] };
                    mma_f16(acc[mt][nt], afr[mt], bfr);
                }
        }
    }

    // ---- epilogue: bias + optional output roll ----
#pragma unroll
    for (int mt = 0; mt < 4; mt++) {
        int m0 = bm + wm + mt * 16 + g;
        int m1 = m0 + 8;
        int bi0 = m0 >> 14, t0 = m0 & 16383;
        int bi1 = m1 >> 14, t1 = m1 & 16383;
        int d0 = ROLL_OUT ? ((t0 + SHIFT) & 16383) : t0;
        int d1 = ROLL_OUT ? ((t1 + SHIFT) & 16383) : t1;
        OutT* row0 = Cout + (size_t)((bi0 << 14) + d0) * Ncols;
        OutT* row1 = Cout + (size_t)((bi1 << 14) + d1) * Ncols;
#pragma unroll
        for (int nt = 0; nt < 4; nt++) {
            int col = bn + wn + nt * 8 + 2 * tg;
            float b0 = bias[col], b1 = bias[col + 1];
            if constexpr (sizeof(OutT) == 4) {
                *(float2*)((float*)row0 + col) =
                    make_float2(acc[mt][nt][0] + b0, acc[mt][nt][1] + b1);
                *(float2*)((float*)row1 + col) =
                    make_float2(acc[mt][nt][2] + b0, acc[mt][nt][3] + b1);
            } else {
                *(uint32_t*)((__half*)row0 + col) =
                    h2u(__floats2half2_rn(acc[mt][nt][0] + b0, acc[mt][nt][1] + b1));
                *(uint32_t*)((__half*)row1 + col) =
                    h2u(__floats2half2_rn(acc[mt][nt][2] + b0, acc[mt][nt][3] + b1));
            }
        }
    }
}

// ---------------------------------------------------------------------------
// cvt pre-passes: fp32 -> fp16
// ---------------------------------------------------------------------------
__global__ void cvt_roll_h_kernel(const float* __restrict__ x, __half* __restrict__ xh)
{
    size_t i4 = (size_t)blockIdx.x * 256 + threadIdx.x;
    size_t fi = i4 * 4;
    int m = (int)(fi >> 8);
    int c = (int)(fi & 255);
    int bi = m >> 14, t = m & 16383;
    int s = (t + SHIFT) & 16383;
    float4 v = *(const float4*)(x + (size_t)((bi << 14) + s) * CDIM + c);
    *(uint2*)(xh + fi) = make_uint2(h2u(__floats2half2_rn(v.x, v.y)),
                                    h2u(__floats2half2_rn(v.z, v.w)));
}

__global__ void cvt_h_kernel(const float* __restrict__ src, __half* __restrict__ dst, int n4)
{
    int i = blockIdx.x * 256 + threadIdx.x;
    if (i < n4) {
        float4 v = *(const float4*)(src + (size_t)i * 4);
        *(uint2*)(dst + (size_t)i * 4) = make_uint2(h2u(__floats2half2_rn(v.x, v.y)),
                                                    h2u(__floats2half2_rn(v.z, v.w)));
    }
}

// ---------------------------------------------------------------------------
// FP16 tensor-core attention (unchanged — passing).
// ---------------------------------------------------------------------------
__global__ void __launch_bounds__(128)
attn_f16_kernel(const __half* __restrict__ qkv,
                const float* __restrict__ rel_pos,
                __half* __restrict__ att)
{
    __shared__ __half Qs[64][40];
    __shared__ __half Ks[64][40];
    __shared__ __half VT[32][72];
    __shared__ __half Ps[64][72];
    __shared__ float  Os[64][36];
    __shared__ float  rels[128];
    __shared__ float  sinv[64];

    const int wi = blockIdx.x;
    const int h  = blockIdx.y;
    const int tid  = threadIdx.x;
    const int w    = tid >> 5;
    const int lane = tid & 31;
    const int g    = lane >> 2;
    const int tg   = lane & 3;
    const int mbase = wi * PWIN;
    const bool lastw = ((wi & (WPB - 1)) == (WPB - 1));

#pragma unroll
    for (int it = 0; it < 2; it++) {
        int idx = tid + it * 128;
        int j = idx >> 2, c8 = (idx & 3) * 8;
        const __half* base = qkv + (size_t)(mbase + j) * QKV_N + h * HDIM + c8;
        uint4 q4 = *(const uint4*)(base);
        uint4 k4 = *(const uint4*)(base + 256);
        uint4 v4 = *(const uint4*)(base + 512);
        *(uint4*)&Qs[j][c8] = q4;
        *(uint4*)&Ks[j][c8] = k4;
        __half vh[8];
        *(uint4*)vh = v4;
#pragma unroll
        for (int d = 0; d < 8; d++) VT[c8 + d][j] = vh[d];
    }
    if (tid < 127) rels[tid] = rel_pos[h * 127 + tid];
    __syncthreads();

    uint32_t qfr[2][4];
    {
        uint32_t qa = smem_u32(&Qs[w * 16 + (lane & 15)][(lane >> 4) * 8]);
        ldsm_x4(qfr[0], qa);
        ldsm_x4(qfr[1], qa + 32);
    }

    float sfr[8][4];
#pragma unroll
    for (int nt = 0; nt < 8; nt++)
#pragma unroll
        for (int r = 0; r < 4; r++) sfr[nt][r] = 0.0f;
    {
        uint32_t kb = smem_u32(&Ks[((lane >> 4) << 3) + (lane & 7)][((lane >> 3) & 1) * 8]);
#pragma unroll
        for (int ks = 0; ks < 2; ks++) {
#pragma unroll
            for (int ntp = 0; ntp < 4; ntp++) {
                uint32_t bb[4];
                ldsm_x4(bb, kb + (uint32_t)(ntp * 16 * 80) + ks * 32);
                uint32_t b0[2] = { bb[0], bb[1] };
                uint32_t b1[2] = { bb[2], bb[3] };
                mma_f16(sfr[ntp * 2],     qfr[ks], b0);
                mma_f16(sfr[ntp * 2 + 1], qfr[ks], b1);
            }
        }
    }

    const float scale = 0.17677669529663687f;
    const int i0 = w * 16 + g;
    const int i1 = i0 + 8;
    const int myside = w >> 1;
    float sum0 = 0.0f, sum1 = 0.0f;
#pragma unroll
    for (int nt = 0; nt < 8; nt++) {
        int j0 = nt * 8 + 2 * tg;
        float e00, e01, e10, e11;
        if (lastw && ((nt >> 2) != myside)) {
            e00 = e01 = e10 = e11 = 0.0f;
        } else {
            e00 = __expf(sfr[nt][0] * scale + rels[i0 - j0 + 63]);
            e01 = __expf(sfr[nt][1] * scale + rels[i0 - j0 + 62]);
            e10 = __expf(sfr[nt][2] * scale + rels[i1 - j0 + 63]);
            e11 = __expf(sfr[nt][3] * scale + rels[i1 - j0 + 62]);
        }
        sum0 += e00 + e01;
        sum1 += e10 + e11;
        *(uint32_t*)&Ps[i0][j0] = h2u(__floats2half2_rn(e00, e01));
        *(uint32_t*)&Ps[i1][j0] = h2u(__floats2half2_rn(e10, e11));
    }
    sum0 += __shfl_xor_sync(0xffffffffu, sum0, 1);
    sum0 += __shfl_xor_sync(0xffffffffu, sum0, 2);
    sum1 += __shfl_xor_sync(0xffffffffu, sum1, 1);
    sum1 += __shfl_xor_sync(0xffffffffu, sum1, 2);
    if (tg == 0) { sinv[i0] = 1.0f / sum0; sinv[i1] = 1.0f / sum1; }
    __syncwarp();

    float ofr[2][2][4];
#pragma unroll
    for (int mt = 0; mt < 2; mt++)
#pragma unroll
        for (int nt = 0; nt < 2; nt++)
#pragma unroll
            for (int r = 0; r < 4; r++) ofr[mt][nt][r] = 0.0f;
    {
        uint32_t va0 = smem_u32(&VT[(lane & 15)][(lane >> 4) * 8]);
        uint32_t va1 = smem_u32(&VT[16 + (lane & 15)][(lane >> 4) * 8]);
        uint32_t pb  = smem_u32(&Ps[w * 16 + ((lane >> 4) << 3) + (lane & 7)]
                                   [((lane >> 3) & 1) * 8]);
#pragma unroll
        for (int ks = 0; ks < 4; ks++) {
            uint32_t a0[4], a1[4], bb[4];
            ldsm_x4(a0, va0 + ks * 32);
            ldsm_x4(a1, va1 + ks * 32);
            ldsm_x4(bb, pb + ks * 32);
            uint32_t b0[2] = { bb[0], bb[1] };
            uint32_t b1[2] = { bb[2], bb[3] };
            mma_f16(ofr[0][0], a0, b0);
            mma_f16(ofr[0][1], a0, b1);
            mma_f16(ofr[1][0], a1, b0);
            mma_f16(ofr[1][1], a1, b1);
        }
    }

#pragma unroll
    for (int mt = 0; mt < 2; mt++)
#pragma unroll
        for (int nt = 0; nt < 2; nt++) {
            int d = mt * 16 + g;
            int i = w * 16 + nt * 8 + 2 * tg;
            Os[i][d]         = ofr[mt][nt][0];
            Os[i + 1][d]     = ofr[mt][nt][1];
            Os[i][d + 8]     = ofr[mt][nt][2];
            Os[i + 1][d + 8] = ofr[mt][nt][3];
        }
    __syncthreads();

#pragma unroll
    for (int it = 0; it < 2; it++) {
        int idx = tid + it * 128;
        int i = idx >> 2, d8 = (idx & 3) * 8;
        float inv = sinv[i];
        float4 v0 = *(float4*)&Os[i][d8];
        float4 v1 = *(float4*)&Os[i][d8 + 4];
        uint4 o;
        o.x = h2u(__floats2half2_rn(v0.x * inv, v0.y * inv));
        o.y = h2u(__floats2half2_rn(v0.z * inv, v0.w * inv));
        o.z = h2u(__floats2half2_rn(v1.x * inv, v1.y * inv));
        o.w = h2u(__floats2half2_rn(v1.z * inv, v1.w * inv));
        *(uint4*)(att + (size_t)(mbase + i) * CDIM + h * HDIM + d8) = o;
    }
}

// ---------------------------------------------------------------------------
extern "C" void kernel_launch(void* const* d_in, const int* in_sizes, int n_in,
                              void* d_out, int out_size)
{
    const float* x       = (const float*)d_in[0];
    const float* w_qkv   = (const float*)d_in[1];
    const float* b_qkv   = (const float*)d_in[2];
    const float* rel_pos = (const float*)d_in[3];
    const float* w_out   = (const float*)d_in[4];
    const float* b_out   = (const float*)d_in[5];
    float* out = (float*)d_out;

    __half *qkvp, *attp, *xhp, *wqkvp, *woutp;
    cudaGetSymbolAddress((void**)&qkvp,  g_qkv);
    cudaGetSymbolAddress((void**)&attp,  g_att);
    cudaGetSymbolAddress((void**)&xhp,   g_xh);
    cudaGetSymbolAddress((void**)&wqkvp, g_wqkvh);
    cudaGetSymbolAddress((void**)&woutp, g_wouth);

    cudaFuncSetAttribute(gemm_f16_kernel<false, __half>,
                         cudaFuncAttributeMaxDynamicSharedMemorySize, GSMEM);
    cudaFuncSetAttribute(gemm_f16_kernel<true, float>,
                         cudaFuncAttributeMaxDynamicSharedMemorySize, GSMEM);

    // K0: fp16 pre-conversion (roll folded into x copy)
    cvt_roll_h_kernel<<<(MTOT * CDIM / 4) / 256, 256>>>(x, xhp);
    cvt_h_kernel<<<(QKV_N * CDIM / 4 + 255) / 256, 256>>>(w_qkv, wqkvp, QKV_N * CDIM / 4);
    cvt_h_kernel<<<(CDIM * CDIM / 4 + 255) / 256, 256>>>(w_out, woutp, CDIM * CDIM / 4);

    // K1: QKV projection (fp16 out)
    {
        dim3 grid(QKV_N / 128, MTOT / 128);   // (6, 1024)
        gemm_f16_kernel<false, __half><<<grid, 256, GSMEM>>>(xhp, wqkvp, b_qkv, qkvp, QKV_N);
    }
    // K2: windowed attention (fp16 tensor cores)
    {
        dim3 grid(NWIN, NHEADS);
        attn_f16_kernel<<<grid, 128>>>(qkvp, rel_pos, attp);
    }
    // K3: output projection (fp32 out, roll on write)
    {
        dim3 grid(CDIM / 128, MTOT / 128);    // (2, 1024)
        gemm_f16_kernel<true, float><<<grid, 256, GSMEM>>>(attp, woutp, b_out, out, CDIM);
    }
}

// round 15
// speedup vs baseline: 1.4668x; 1.4668x over previous
#include <cuda_runtime.h>
#include <cuda_fp16.h>
#include <cstdint>

// ---------------------------------------------------------------------------
// Shifted-window MSA. B=8, NSEQ=16384, C=256, P=64, SHIFT=32, NH=8, HD=32.
//   K0: fused cvt: x(rolled)->fp16, w_qkv->fp16, w_out->fp16 (ONE launch)
//   K1: QKV GEMM (fp16 mma, 128x128, cp.async 2-stage)  -> g_qkv (fp16)
//   K2: attention (fp16 mma; Ps/Os aliased, 25KB smem)  -> g_att (fp16)
//   K3: out GEMM (same, roll on write)                  -> d_out (fp32)
// tcgen05 unusable: harness ptxas targets sm_103 (no 'a' features).
// GEMM identical to R10 (best measured: K1=199us).
// ---------------------------------------------------------------------------

#define BATCH   8
#define NSEQ    16384
#define CDIM    256
#define PWIN    64
#define SHIFT   32
#define NHEADS  8
#define HDIM    32
#define MTOT    (BATCH * NSEQ)
#define QKV_N   768
#define NWIN    (MTOT / PWIN)
#define WPB     (NSEQ / PWIN)

__device__ __half g_qkv [(size_t)MTOT * QKV_N];
__device__ __half g_att [(size_t)MTOT * CDIM];
__device__ __half g_xh  [(size_t)MTOT * CDIM];
__device__ __half g_wqkvh[(size_t)QKV_N * CDIM];
__device__ __half g_wouth[(size_t)CDIM * CDIM];

// ---------------------------------------------------------------------------
__device__ __forceinline__ uint32_t smem_u32(const void* p) {
    return (uint32_t)__cvta_generic_to_shared(p);
}
__device__ __forceinline__ void mma_f16(float (&d)[4],
                                        const uint32_t (&a)[4],
                                        const uint32_t (&b)[2]) {
    asm volatile(
        "mma.sync.aligned.m16n8k16.row.col.f32.f16.f16.f32 "
        "{%0,%1,%2,%3}, {%4,%5,%6,%7}, {%8,%9}, {%0,%1,%2,%3};"
        : "+f"(d[0]), "+f"(d[1]), "+f"(d[2]), "+f"(d[3])
        : "r"(a[0]), "r"(a[1]), "r"(a[2]), "r"(a[3]), "r"(b[0]), "r"(b[1]));
}
__device__ __forceinline__ void ldsm_x4(uint32_t (&r)[4], uint32_t addr) {
    asm volatile("ldmatrix.sync.aligned.m8n8.x4.shared.b16 {%0,%1,%2,%3}, [%4];"
        : "=r"(r[0]), "=r"(r[1]), "=r"(r[2]), "=r"(r[3]) : "r"(addr));
}
__device__ __forceinline__ uint32_t h2u(__half2 h) {
    return *reinterpret_cast<uint32_t*>(&h);
}
__device__ __forceinline__ void cp_async16(uint32_t dst, const void* src) {
    asm volatile("cp.async.cg.shared.global [%0], [%1], 16;"
                 :: "r"(dst), "l"(src));
}
#define CP_COMMIT() asm volatile("cp.async.commit_group;" ::: "memory")
#define CP_WAIT(n)  asm volatile("cp.async.wait_group %0;" :: "n"(n) : "memory")

// ---------------------------------------------------------------------------
// FP16 GEMM — identical to R10 (best measured config).
// BM=BN=128, BK=64, 256 threads = 8 warps, warp tile 64x32, 2-stage cp.async.
// ---------------------------------------------------------------------------
#define HBK 64
#define NKT (CDIM / HBK)            // 4
#define ROWB 144                    // row stride bytes
#define STG_B (2 * 128 * ROWB)      // stage stride = 36864 B
#define BOFF (128 * ROWB)           // B matrix offset within stage = 18432 B
#define GSMEM (2 * STG_B)           // 73728 B

template<bool ROLL_OUT, typename OutT>
__global__ void __launch_bounds__(256, 2)
gemm_f16_kernel(const __half* __restrict__ A,
                const __half* __restrict__ W,
                const float* __restrict__ bias,
                OutT* __restrict__ Cout,
                int Ncols)
{
    extern __shared__ __half smem[];
    const uint32_t sbase = smem_u32(smem);

    const int bm = blockIdx.y * 128;
    const int bn = blockIdx.x * 128;

    const int t    = threadIdx.x;
    const int warp = t >> 5;
    const int lane = t & 31;
    const int g    = lane >> 2;
    const int tg   = lane & 3;

    const int wm = (warp & 1) * 64;
    const int wn = (warp >> 1) * 32;

    int arow[4], ac[4];
#pragma unroll
    for (int i = 0; i < 4; i++) {
        int id = t + i * 256;
        arow[i] = id >> 3;
        ac[i]   = id & 7;
    }
    const __half* Ab = A + (size_t)bm * CDIM;
    const __half* Wb = W + (size_t)bn * CDIM;

    uint32_t dstA[4];
#pragma unroll
    for (int i = 0; i < 4; i++)
        dstA[i] = sbase + (uint32_t)(arow[i] * ROWB + ac[i] * 16);

    uint32_t aAddr[4], bAddr[2];
#pragma unroll
    for (int mt = 0; mt < 4; mt++)
        aAddr[mt] = sbase + (uint32_t)((wm + mt * 16 + (lane & 15)) * ROWB
                                       + (lane >> 4) * 16);
#pragma unroll
    for (int ntp = 0; ntp < 2; ntp++)
        bAddr[ntp] = sbase + BOFF
                   + (uint32_t)((wn + ntp * 16 + ((lane >> 4) << 3) + (lane & 7)) * ROWB
                                + ((lane >> 3) & 1) * 16);

    float acc[4][4][4];
#pragma unroll
    for (int mt = 0; mt < 4; mt++)
#pragma unroll
        for (int nt = 0; nt < 4; nt++)
#pragma unroll
            for (int r = 0; r < 4; r++) acc[mt][nt][r] = 0.0f;

    // prologue: stages 0 and 1
#pragma unroll
    for (int i = 0; i < 4; i++) {
        cp_async16(dstA[i],        Ab + (size_t)arow[i] * CDIM + ac[i] * 8);
        cp_async16(dstA[i] + BOFF, Wb + (size_t)arow[i] * CDIM + ac[i] * 8);
    }
    CP_COMMIT();
#pragma unroll
    for (int i = 0; i < 4; i++) {
        cp_async16(dstA[i] + STG_B,        Ab + (size_t)arow[i] * CDIM + HBK + ac[i] * 8);
        cp_async16(dstA[i] + STG_B + BOFF, Wb + (size_t)arow[i] * CDIM + HBK + ac[i] * 8);
    }
    CP_COMMIT();

#pragma unroll 1
    for (int kt = 0; kt < NKT; kt++) {
        if (kt < NKT - 1) CP_WAIT(1);
        else              CP_WAIT(0);
        __syncthreads();

        const uint32_t so = (kt & 1) ? (uint32_t)STG_B : 0u;
#pragma unroll
        for (int ks = 0; ks < 4; ks++) {
            const uint32_t koff = ks * 32;
            uint32_t afr[4][4], bp[2][4];
#pragma unroll
            for (int mt = 0; mt < 4; mt++) ldsm_x4(afr[mt], aAddr[mt] + so + koff);
#pragma unroll
            for (int ntp = 0; ntp < 2; ntp++) ldsm_x4(bp[ntp], bAddr[ntp] + so + koff);
#pragma unroll
            for (int mt = 0; mt < 4; mt++)
#pragma unroll
                for (int nt = 0; nt < 4; nt++) {
                    uint32_t bfr[2] = { bp[nt >> 1][(nt & 1) * 2],
                                        bp[nt >> 1][(nt & 1) * 2 + 1] };
                    mma_f16(acc[mt][nt], afr[mt], bfr);
                }
        }

        if (kt + 2 < NKT) {
            __syncthreads();
            const int k0 = (kt + 2) * HBK;
#pragma unroll
            for (int i = 0; i < 4; i++) {
                cp_async16(dstA[i] + so,        Ab + (size_t)arow[i] * CDIM + k0 + ac[i] * 8);
                cp_async16(dstA[i] + so + BOFF, Wb + (size_t)arow[i] * CDIM + k0 + ac[i] * 8);
            }
            CP_COMMIT();
        }
    }

    // epilogue: bias + optional output roll
#pragma unroll
    for (int mt = 0; mt < 4; mt++) {
        int m0 = bm + wm + mt * 16 + g;
        int m1 = m0 + 8;
        int bi0 = m0 >> 14, t0 = m0 & 16383;
        int bi1 = m1 >> 14, t1 = m1 & 16383;
        int d0 = ROLL_OUT ? ((t0 + SHIFT) & 16383) : t0;
        int d1 = ROLL_OUT ? ((t1 + SHIFT) & 16383) : t1;
        OutT* row0 = Cout + (size_t)((bi0 << 14) + d0) * Ncols;
        OutT* row1 = Cout + (size_t)((bi1 << 14) + d1) * Ncols;
#pragma unroll
        for (int nt = 0; nt < 4; nt++) {
            int col = bn + wn + nt * 8 + 2 * tg;
            float b0 = bias[col], b1 = bias[col + 1];
            if constexpr (sizeof(OutT) == 4) {
                *(float2*)((float*)row0 + col) =
                    make_float2(acc[mt][nt][0] + b0, acc[mt][nt][1] + b1);
                *(float2*)((float*)row1 + col) =
                    make_float2(acc[mt][nt][2] + b0, acc[mt][nt][3] + b1);
            } else {
                *(uint32_t*)((__half*)row0 + col) =
                    h2u(__floats2half2_rn(acc[mt][nt][0] + b0, acc[mt][nt][1] + b1));
                *(uint32_t*)((__half*)row1 + col) =
                    h2u(__floats2half2_rn(acc[mt][nt][2] + b0, acc[mt][nt][3] + b1));
            }
        }
    }
}

// ---------------------------------------------------------------------------
// Fused cvt pre-pass (ONE launch): x(rolled)->g_xh, w_qkv->g_wqkvh, w_out->g_wouth.
// Grid covers all float4 elements: 8388608 + 49152 + 16384 = 8454144 / 256 = 33024.
// ---------------------------------------------------------------------------
#define XN4  (MTOT * CDIM / 4)          // 8388608
#define WQ4  (QKV_N * CDIM / 4)         // 49152
#define WO4  (CDIM * CDIM / 4)          // 16384

__global__ void cvt_all_kernel(const float* __restrict__ x,
                               const float* __restrict__ w_qkv,
                               const float* __restrict__ w_out,
                               __half* __restrict__ xh,
                               __half* __restrict__ wqkvh,
                               __half* __restrict__ wouth)
{
    size_t i4 = (size_t)blockIdx.x * 256 + threadIdx.x;
    if (i4 < (size_t)XN4) {
        size_t fi = i4 * 4;
        int m = (int)(fi >> 8);
        int c = (int)(fi & 255);
        int bi = m >> 14, t = m & 16383;
        int s = (t + SHIFT) & 16383;
        float4 v = *(const float4*)(x + (size_t)((bi << 14) + s) * CDIM + c);
        *(uint2*)(xh + fi) = make_uint2(h2u(__floats2half2_rn(v.x, v.y)),
                                        h2u(__floats2half2_rn(v.z, v.w)));
    } else if (i4 < (size_t)(XN4 + WQ4)) {
        size_t j = i4 - XN4;
        float4 v = *(const float4*)(w_qkv + j * 4);
        *(uint2*)(wqkvh + j * 4) = make_uint2(h2u(__floats2half2_rn(v.x, v.y)),
                                              h2u(__floats2half2_rn(v.z, v.w)));
    } else {
        size_t j = i4 - XN4 - WQ4;
        float4 v = *(const float4*)(w_out + j * 4);
        *(uint2*)(wouth + j * 4) = make_uint2(h2u(__floats2half2_rn(v.x, v.y)),
                                              h2u(__floats2half2_rn(v.z, v.w)));
    }
}

// ---------------------------------------------------------------------------
// FP16 tensor-core attention. Same algorithm as R10; Os staging now ALIASES
// the Ps buffer (both 9216 B) -> smem ~25KB -> 9 blocks/SM (was 6).
// Safe without extra barrier: each warp's PV ldsm reads of its own Ps rows
// complete (in-warp program order) before its Os writes to the same rows;
// other warps never touch those rows. Final epilogue reads follow the
// existing __syncthreads.
// ---------------------------------------------------------------------------
__global__ void __launch_bounds__(128)
attn_f16_kernel(const __half* __restrict__ qkv,
                const float* __restrict__ rel_pos,
                __half* __restrict__ att)
{
    __shared__ __half Qs[64][40];
    __shared__ __half Ks[64][40];
    __shared__ __half VT[32][72];
    __shared__ __align__(16) __half Ps[64][72];   // aliased as float Os[64][36]
    __shared__ float  rels[128];
    __shared__ float  sinv[64];

    float (*Os)[36] = reinterpret_cast<float (*)[36]>(&Ps[0][0]);

    const int wi = blockIdx.x;
    const int h  = blockIdx.y;
    const int tid  = threadIdx.x;
    const int w    = tid >> 5;
    const int lane = tid & 31;
    const int g    = lane >> 2;
    const int tg   = lane & 3;
    const int mbase = wi * PWIN;
    const bool lastw = ((wi & (WPB - 1)) == (WPB - 1));

#pragma unroll
    for (int it = 0; it < 2; it++) {
        int idx = tid + it * 128;
        int j = idx >> 2, c8 = (idx & 3) * 8;
        const __half* base = qkv + (size_t)(mbase + j) * QKV_N + h * HDIM + c8;
        uint4 q4 = *(const uint4*)(base);
        uint4 k4 = *(const uint4*)(base + 256);
        uint4 v4 = *(const uint4*)(base + 512);
        *(uint4*)&Qs[j][c8] = q4;
        *(uint4*)&Ks[j][c8] = k4;
        __half vh[8];
        *(uint4*)vh = v4;
#pragma unroll
        for (int d = 0; d < 8; d++) VT[c8 + d][j] = vh[d];
    }
    if (tid < 127) rels[tid] = rel_pos[h * 127 + tid];
    __syncthreads();

    uint32_t qfr[2][4];
    {
        uint32_t qa = smem_u32(&Qs[w * 16 + (lane & 15)][(lane >> 4) * 8]);
        ldsm_x4(qfr[0], qa);
        ldsm_x4(qfr[1], qa + 32);
    }

    float sfr[8][4];
#pragma unroll
    for (int nt = 0; nt < 8; nt++)
#pragma unroll
        for (int r = 0; r < 4; r++) sfr[nt][r] = 0.0f;
    {
        uint32_t kb = smem_u32(&Ks[((lane >> 4) << 3) + (lane & 7)][((lane >> 3) & 1) * 8]);
#pragma unroll
        for (int ks = 0; ks < 2; ks++) {
#pragma unroll
            for (int ntp = 0; ntp < 4; ntp++) {
                uint32_t bb[4];
                ldsm_x4(bb, kb + (uint32_t)(ntp * 16 * 80) + ks * 32);
                uint32_t b0[2] = { bb[0], bb[1] };
                uint32_t b1[2] = { bb[2], bb[3] };
                mma_f16(sfr[ntp * 2],     qfr[ks], b0);
                mma_f16(sfr[ntp * 2 + 1], qfr[ks], b1);
            }
        }
    }

    const float scale = 0.17677669529663687f;
    const int i0 = w * 16 + g;
    const int i1 = i0 + 8;
    const int myside = w >> 1;
    float sum0 = 0.0f, sum1 = 0.0f;
#pragma unroll
    for (int nt = 0; nt < 8; nt++) {
        int j0 = nt * 8 + 2 * tg;
        float e00, e01, e10, e11;
        if (lastw && ((nt >> 2) != myside)) {
            e00 = e01 = e10 = e11 = 0.0f;
        } else {
            e00 = __expf(sfr[nt][0] * scale + rels[i0 - j0 + 63]);
            e01 = __expf(sfr[nt][1] * scale + rels[i0 - j0 + 62]);
            e10 = __expf(sfr[nt][2] * scale + rels[i1 - j0 + 63]);
            e11 = __expf(sfr[nt][3] * scale + rels[i1 - j0 + 62]);
        }
        sum0 += e00 + e01;
        sum1 += e10 + e11;
        *(uint32_t*)&Ps[i0][j0] = h2u(__floats2half2_rn(e00, e01));
        *(uint32_t*)&Ps[i1][j0] = h2u(__floats2half2_rn(e10, e11));
    }
    sum0 += __shfl_xor_sync(0xffffffffu, sum0, 1);
    sum0 += __shfl_xor_sync(0xffffffffu, sum0, 2);
    sum1 += __shfl_xor_sync(0xffffffffu, sum1, 1);
    sum1 += __shfl_xor_sync(0xffffffffu, sum1, 2);
    if (tg == 0) { sinv[i0] = 1.0f / sum0; sinv[i1] = 1.0f / sum1; }
    __syncwarp();

    float ofr[2][2][4];
#pragma unroll
    for (int mt = 0; mt < 2; mt++)
#pragma unroll
        for (int nt = 0; nt < 2; nt++)
#pragma unroll
            for (int r = 0; r < 4; r++) ofr[mt][nt][r] = 0.0f;
    {
        uint32_t va0 = smem_u32(&VT[(lane & 15)][(lane >> 4) * 8]);
        uint32_t va1 = smem_u32(&VT[16 + (lane & 15)][(lane >> 4) * 8]);
        uint32_t pb  = smem_u32(&Ps[w * 16 + ((lane >> 4) << 3) + (lane & 7)]
                                   [((lane >> 3) & 1) * 8]);
#pragma unroll
        for (int ks = 0; ks < 4; ks++) {
            uint32_t a0[4], a1[4], bb[4];
            ldsm_x4(a0, va0 + ks * 32);
            ldsm_x4(a1, va1 + ks * 32);
            ldsm_x4(bb, pb + ks * 32);
            uint32_t b0[2] = { bb[0], bb[1] };
            uint32_t b1[2] = { bb[2], bb[3] };
            mma_f16(ofr[0][0], a0, b0);
            mma_f16(ofr[0][1], a0, b1);
            mma_f16(ofr[1][0], a1, b0);
            mma_f16(ofr[1][1], a1, b1);
        }
    }

    // transpose via aliased fp32 staging (own rows only), normalize, write
#pragma unroll
    for (int mt = 0; mt < 2; mt++)
#pragma unroll
        for (int nt = 0; nt < 2; nt++) {
            int d = mt * 16 + g;
            int i = w * 16 + nt * 8 + 2 * tg;
            Os[i][d]         = ofr[mt][nt][0];
            Os[i + 1][d]     = ofr[mt][nt][1];
            Os[i][d + 8]     = ofr[mt][nt][2];
            Os[i + 1][d + 8] = ofr[mt][nt][3];
        }
    __syncthreads();

#pragma unroll
    for (int it = 0; it < 2; it++) {
        int idx = tid + it * 128;
        int i = idx >> 2, d8 = (idx & 3) * 8;
        float inv = sinv[i];
        float4 v0 = *(float4*)&Os[i][d8];
        float4 v1 = *(float4*)&Os[i][d8 + 4];
        uint4 o;
        o.x = h2u(__floats2half2_rn(v0.x * inv, v0.y * inv));
        o.y = h2u(__floats2half2_rn(v0.z * inv, v0.w * inv));
        o.z = h2u(__floats2half2_rn(v1.x * inv, v1.y * inv));
        o.w = h2u(__floats2half2_rn(v1.z * inv, v1.w * inv));
        *(uint4*)(att + (size_t)(mbase + i) * CDIM + h * HDIM + d8) = o;
    }
}

// ---------------------------------------------------------------------------
extern "C" void kernel_launch(void* const* d_in, const int* in_sizes, int n_in,
                              void* d_out, int out_size)
{
    const float* x       = (const float*)d_in[0];
    const float* w_qkv   = (const float*)d_in[1];
    const float* b_qkv   = (const float*)d_in[2];
    const float* rel_pos = (const float*)d_in[3];
    const float* w_out   = (const float*)d_in[4];
    const float* b_out   = (const float*)d_in[5];
    float* out = (float*)d_out;

    __half *qkvp, *attp, *xhp, *wqkvp, *woutp;
    cudaGetSymbolAddress((void**)&qkvp,  g_qkv);
    cudaGetSymbolAddress((void**)&attp,  g_att);
    cudaGetSymbolAddress((void**)&xhp,   g_xh);
    cudaGetSymbolAddress((void**)&wqkvp, g_wqkvh);
    cudaGetSymbolAddress((void**)&woutp, g_wouth);

    cudaFuncSetAttribute(gemm_f16_kernel<false, __half>,
                         cudaFuncAttributeMaxDynamicSharedMemorySize, GSMEM);
    cudaFuncSetAttribute(gemm_f16_kernel<true, float>,
                         cudaFuncAttributeMaxDynamicSharedMemorySize, GSMEM);

    // K0: fused fp16 pre-conversion (roll folded into x copy), one launch
    {
        int grid = (XN4 + WQ4 + WO4) / 256;   // 33024
        cvt_all_kernel<<<grid, 256>>>(x, w_qkv, w_out, xhp, wqkvp, woutp);
    }
    // K1: QKV projection (fp16 out)
    {
        dim3 grid(QKV_N / 128, MTOT / 128);   // (6, 1024)
        gemm_f16_kernel<false, __half><<<grid, 256, GSMEM>>>(xhp, wqkvp, b_qkv, qkvp, QKV_N);
    }
    // K2: windowed attention (fp16 tensor cores)
    {
        dim3 grid(NWIN, NHEADS);
        attn_f16_kernel<<<grid, 128>>>(qkvp, rel_pos, attp);
    }
    // K3: output projection (fp32 out, roll on write)
    {
        dim3 grid(CDIM / 128, MTOT / 128);    // (2, 1024)
        gemm_f16_kernel<true, float><<<grid, 256, GSMEM>>>(attp, woutp, b_out, out, CDIM);
    }
}

// round 16
// speedup vs baseline: 1.5468x; 1.0545x over previous
#include <cuda_runtime.h>
#include <cuda_fp16.h>
#include <cstdint>

// ---------------------------------------------------------------------------
// Shifted-window MSA. B=8, NSEQ=16384, C=256, P=64, SHIFT=32, NH=8, HD=32.
//   K0: fused cvt: x(rolled)->fp16, w_qkv->fp16, w_out->fp16 (ONE launch)
//   K1: QKV GEMM (fp16 mma, 128x128, cp.async 2-stage)  -> g_qkv (fp16)
//   K2: attention (fp16 mma; ldsm.trans V; Ps aliased on Qs/Ks; ~16KB smem)
//   K3: out GEMM (same, roll on write)                  -> d_out (fp32)
// tcgen05 unusable: harness ptxas targets sm_103 (no 'a' features).
// GEMM identical to R10/R14 (best measured: K1=199us, K3=66us).
// ---------------------------------------------------------------------------

#define BATCH   8
#define NSEQ    16384
#define CDIM    256
#define PWIN    64
#define SHIFT   32
#define NHEADS  8
#define HDIM    32
#define MTOT    (BATCH * NSEQ)
#define QKV_N   768
#define NWIN    (MTOT / PWIN)
#define WPB     (NSEQ / PWIN)

__device__ __half g_qkv [(size_t)MTOT * QKV_N];
__device__ __half g_att [(size_t)MTOT * CDIM];
__device__ __half g_xh  [(size_t)MTOT * CDIM];
__device__ __half g_wqkvh[(size_t)QKV_N * CDIM];
__device__ __half g_wouth[(size_t)CDIM * CDIM];

// ---------------------------------------------------------------------------
__device__ __forceinline__ uint32_t smem_u32(const void* p) {
    return (uint32_t)__cvta_generic_to_shared(p);
}
__device__ __forceinline__ void mma_f16(float (&d)[4],
                                        const uint32_t (&a)[4],
                                        const uint32_t (&b)[2]) {
    asm volatile(
        "mma.sync.aligned.m16n8k16.row.col.f32.f16.f16.f32 "
        "{%0,%1,%2,%3}, {%4,%5,%6,%7}, {%8,%9}, {%0,%1,%2,%3};"
        : "+f"(d[0]), "+f"(d[1]), "+f"(d[2]), "+f"(d[3])
        : "r"(a[0]), "r"(a[1]), "r"(a[2]), "r"(a[3]), "r"(b[0]), "r"(b[1]));
}
__device__ __forceinline__ void ldsm_x4(uint32_t (&r)[4], uint32_t addr) {
    asm volatile("ldmatrix.sync.aligned.m8n8.x4.shared.b16 {%0,%1,%2,%3}, [%4];"
        : "=r"(r[0]), "=r"(r[1]), "=r"(r[2]), "=r"(r[3]) : "r"(addr));
}
__device__ __forceinline__ void ldsm_x4_trans(uint32_t (&r)[4], uint32_t addr) {
    asm volatile("ldmatrix.sync.aligned.m8n8.x4.trans.shared.b16 {%0,%1,%2,%3}, [%4];"
        : "=r"(r[0]), "=r"(r[1]), "=r"(r[2]), "=r"(r[3]) : "r"(addr));
}
__device__ __forceinline__ uint32_t h2u(__half2 h) {
    return *reinterpret_cast<uint32_t*>(&h);
}
__device__ __forceinline__ void cp_async16(uint32_t dst, const void* src) {
    asm volatile("cp.async.cg.shared.global [%0], [%1], 16;"
                 :: "r"(dst), "l"(src));
}
#define CP_COMMIT() asm volatile("cp.async.commit_group;" ::: "memory")
#define CP_WAIT(n)  asm volatile("cp.async.wait_group %0;" :: "n"(n) : "memory")

// ---------------------------------------------------------------------------
// FP16 GEMM — identical to R10/R14 (best measured config).
// ---------------------------------------------------------------------------
#define HBK 64
#define NKT (CDIM / HBK)            // 4
#define ROWB 144                    // row stride bytes
#define STG_B (2 * 128 * ROWB)      // stage stride = 36864 B
#define BOFF (128 * ROWB)           // B matrix offset within stage = 18432 B
#define GSMEM (2 * STG_B)           // 73728 B

template<bool ROLL_OUT, typename OutT>
__global__ void __launch_bounds__(256, 2)
gemm_f16_kernel(const __half* __restrict__ A,
                const __half* __restrict__ W,
                const float* __restrict__ bias,
                OutT* __restrict__ Cout,
                int Ncols)
{
    extern __shared__ __half smem[];
    const uint32_t sbase = smem_u32(smem);

    const int bm = blockIdx.y * 128;
    const int bn = blockIdx.x * 128;

    const int t    = threadIdx.x;
    const int warp = t >> 5;
    const int lane = t & 31;
    const int g    = lane >> 2;
    const int tg   = lane & 3;

    const int wm = (warp & 1) * 64;
    const int wn = (warp >> 1) * 32;

    int arow[4], ac[4];
#pragma unroll
    for (int i = 0; i < 4; i++) {
        int id = t + i * 256;
        arow[i] = id >> 3;
        ac[i]   = id & 7;
    }
    const __half* Ab = A + (size_t)bm * CDIM;
    const __half* Wb = W + (size_t)bn * CDIM;

    uint32_t dstA[4];
#pragma unroll
    for (int i = 0; i < 4; i++)
        dstA[i] = sbase + (uint32_t)(arow[i] * ROWB + ac[i] * 16);

    uint32_t aAddr[4], bAddr[2];
#pragma unroll
    for (int mt = 0; mt < 4; mt++)
        aAddr[mt] = sbase + (uint32_t)((wm + mt * 16 + (lane & 15)) * ROWB
                                       + (lane >> 4) * 16);
#pragma unroll
    for (int ntp = 0; ntp < 2; ntp++)
        bAddr[ntp] = sbase + BOFF
                   + (uint32_t)((wn + ntp * 16 + ((lane >> 4) << 3) + (lane & 7)) * ROWB
                                + ((lane >> 3) & 1) * 16);

    float acc[4][4][4];
#pragma unroll
    for (int mt = 0; mt < 4; mt++)
#pragma unroll
        for (int nt = 0; nt < 4; nt++)
#pragma unroll
            for (int r = 0; r < 4; r++) acc[mt][nt][r] = 0.0f;

#pragma unroll
    for (int i = 0; i < 4; i++) {
        cp_async16(dstA[i],        Ab + (size_t)arow[i] * CDIM + ac[i] * 8);
        cp_async16(dstA[i] + BOFF, Wb + (size_t)arow[i] * CDIM + ac[i] * 8);
    }
    CP_COMMIT();
#pragma unroll
    for (int i = 0; i < 4; i++) {
        cp_async16(dstA[i] + STG_B,        Ab + (size_t)arow[i] * CDIM + HBK + ac[i] * 8);
        cp_async16(dstA[i] + STG_B + BOFF, Wb + (size_t)arow[i] * CDIM + HBK + ac[i] * 8);
    }
    CP_COMMIT();

#pragma unroll 1
    for (int kt = 0; kt < NKT; kt++) {
        if (kt < NKT - 1) CP_WAIT(1);
        else              CP_WAIT(0);
        __syncthreads();

        const uint32_t so = (kt & 1) ? (uint32_t)STG_B : 0u;
#pragma unroll
        for (int ks = 0; ks < 4; ks++) {
            const uint32_t koff = ks * 32;
            uint32_t afr[4][4], bp[2][4];
#pragma unroll
            for (int mt = 0; mt < 4; mt++) ldsm_x4(afr[mt], aAddr[mt] + so + koff);
#pragma unroll
            for (int ntp = 0; ntp < 2; ntp++) ldsm_x4(bp[ntp], bAddr[ntp] + so + koff);
#pragma unroll
            for (int mt = 0; mt < 4; mt++)
#pragma unroll
                for (int nt = 0; nt < 4; nt++) {
                    uint32_t bfr[2] = { bp[nt >> 1][(nt & 1) * 2],
                                        bp[nt >> 1][(nt & 1) * 2 + 1] };
                    mma_f16(acc[mt][nt], afr[mt], bfr);
                }
        }

        if (kt + 2 < NKT) {
            __syncthreads();
            const int k0 = (kt + 2) * HBK;
#pragma unroll
            for (int i = 0; i < 4; i++) {
                cp_async16(dstA[i] + so,        Ab + (size_t)arow[i] * CDIM + k0 + ac[i] * 8);
                cp_async16(dstA[i] + so + BOFF, Wb + (size_t)arow[i] * CDIM + k0 + ac[i] * 8);
            }
            CP_COMMIT();
        }
    }

#pragma unroll
    for (int mt = 0; mt < 4; mt++) {
        int m0 = bm + wm + mt * 16 + g;
        int m1 = m0 + 8;
        int bi0 = m0 >> 14, t0 = m0 & 16383;
        int bi1 = m1 >> 14, t1 = m1 & 16383;
        int d0 = ROLL_OUT ? ((t0 + SHIFT) & 16383) : t0;
        int d1 = ROLL_OUT ? ((t1 + SHIFT) & 16383) : t1;
        OutT* row0 = Cout + (size_t)((bi0 << 14) + d0) * Ncols;
        OutT* row1 = Cout + (size_t)((bi1 << 14) + d1) * Ncols;
#pragma unroll
        for (int nt = 0; nt < 4; nt++) {
            int col = bn + wn + nt * 8 + 2 * tg;
            float b0 = bias[col], b1 = bias[col + 1];
            if constexpr (sizeof(OutT) == 4) {
                *(float2*)((float*)row0 + col) =
                    make_float2(acc[mt][nt][0] + b0, acc[mt][nt][1] + b1);
                *(float2*)((float*)row1 + col) =
                    make_float2(acc[mt][nt][2] + b0, acc[mt][nt][3] + b1);
            } else {
                *(uint32_t*)((__half*)row0 + col) =
                    h2u(__floats2half2_rn(acc[mt][nt][0] + b0, acc[mt][nt][1] + b1));
                *(uint32_t*)((__half*)row1 + col) =
                    h2u(__floats2half2_rn(acc[mt][nt][2] + b0, acc[mt][nt][3] + b1));
            }
        }
    }
}

// ---------------------------------------------------------------------------
// Fused cvt pre-pass (ONE launch) — identical to R14.
// ---------------------------------------------------------------------------
#define XN4  (MTOT * CDIM / 4)          // 8388608
#define WQ4  (QKV_N * CDIM / 4)         // 49152
#define WO4  (CDIM * CDIM / 4)          // 16384

__global__ void cvt_all_kernel(const float* __restrict__ x,
                               const float* __restrict__ w_qkv,
                               const float* __restrict__ w_out,
                               __half* __restrict__ xh,
                               __half* __restrict__ wqkvh,
                               __half* __restrict__ wouth)
{
    size_t i4 = (size_t)blockIdx.x * 256 + threadIdx.x;
    if (i4 < (size_t)XN4) {
        size_t fi = i4 * 4;
        int m = (int)(fi >> 8);
        int c = (int)(fi & 255);
        int bi = m >> 14, t = m & 16383;
        int s = (t + SHIFT) & 16383;
        float4 v = *(const float4*)(x + (size_t)((bi << 14) + s) * CDIM + c);
        *(uint2*)(xh + fi) = make_uint2(h2u(__floats2half2_rn(v.x, v.y)),
                                        h2u(__floats2half2_rn(v.z, v.w)));
    } else if (i4 < (size_t)(XN4 + WQ4)) {
        size_t j = i4 - XN4;
        float4 v = *(const float4*)(w_qkv + j * 4);
        *(uint2*)(wqkvh + j * 4) = make_uint2(h2u(__floats2half2_rn(v.x, v.y)),
                                              h2u(__floats2half2_rn(v.z, v.w)));
    } else {
        size_t j = i4 - XN4 - WQ4;
        float4 v = *(const float4*)(w_out + j * 4);
        *(uint2*)(wouth + j * 4) = make_uint2(h2u(__floats2half2_rn(v.x, v.y)),
                                              h2u(__floats2half2_rn(v.z, v.w)));
    }
}

// ---------------------------------------------------------------------------
// FP16 tensor-core attention (v2):
//  - V stored row-major like K (uint4 staging, no scalar transpose);
//    PV A-operand (V^T) loaded via ldmatrix.x4.trans:
//      row = jbase + ((lane>>4)<<3) + (lane&7), col = ((lane>>3)&1)*16 B,
//      d-tile at +32 B, ks step = 16 rows = 16*80 B.
//  - Ps (and fp32 Os) alias the Qs+Ks region (Q frags are in regs after the
//    first ldsm; K is dead after the S MMAs; one __syncthreads guards the
//    overwrite). Smem ~15.9 KB.
// ---------------------------------------------------------------------------
__global__ void __launch_bounds__(128)
attn_f16_kernel(const __half* __restrict__ qkv,
                const float* __restrict__ rel_pos,
                __half* __restrict__ att)
{
    __shared__ __align__(16) __half QKpool[2 * 64 * 40];  // 10240 B
    __shared__ __align__(16) __half Vs[64][40];           // 5120 B
    __shared__ float  rels[128];
    __shared__ float  sinv[64];

    __half (*Qs)[40] = reinterpret_cast<__half (*)[40]>(QKpool);
    __half (*Ks)[40] = reinterpret_cast<__half (*)[40]>(QKpool + 64 * 40);
    __half (*Ps)[72] = reinterpret_cast<__half (*)[72]>(QKpool);  // 9216 B alias
    float  (*Os)[36] = reinterpret_cast<float (*)[36]>(QKpool);   // alias of Ps

    const int wi = blockIdx.x;
    const int h  = blockIdx.y;
    const int tid  = threadIdx.x;
    const int w    = tid >> 5;
    const int lane = tid & 31;
    const int g    = lane >> 2;
    const int tg   = lane & 3;
    const int mbase = wi * PWIN;
    const bool lastw = ((wi & (WPB - 1)) == (WPB - 1));

    // ---- stage Q, K, V (all row-major [j][d], uint4 per thread) ----
#pragma unroll
    for (int it = 0; it < 2; it++) {
        int idx = tid + it * 128;
        int j = idx >> 2, c8 = (idx & 3) * 8;
        const __half* base = qkv + (size_t)(mbase + j) * QKV_N + h * HDIM + c8;
        uint4 q4 = *(const uint4*)(base);
        uint4 k4 = *(const uint4*)(base + 256);
        uint4 v4 = *(const uint4*)(base + 512);
        *(uint4*)&Qs[j][c8] = q4;
        *(uint4*)&Ks[j][c8] = k4;
        *(uint4*)&Vs[j][c8] = v4;
    }
    if (tid < 127) rels[tid] = rel_pos[h * 127 + tid];
    __syncthreads();

    // ---- Q fragments (held in regs; Qs dead afterwards) ----
    uint32_t qfr[2][4];
    {
        uint32_t qa = smem_u32(&Qs[w * 16 + (lane & 15)][(lane >> 4) * 8]);
        ldsm_x4(qfr[0], qa);
        ldsm_x4(qfr[1], qa + 32);
    }

    // ---- S = Q K^T ----
    float sfr[8][4];
#pragma unroll
    for (int nt = 0; nt < 8; nt++)
#pragma unroll
        for (int r = 0; r < 4; r++) sfr[nt][r] = 0.0f;
    {
        uint32_t kb = smem_u32(&Ks[((lane >> 4) << 3) + (lane & 7)][((lane >> 3) & 1) * 8]);
#pragma unroll
        for (int ks = 0; ks < 2; ks++) {
#pragma unroll
            for (int ntp = 0; ntp < 4; ntp++) {
                uint32_t bb[4];
                ldsm_x4(bb, kb + (uint32_t)(ntp * 16 * 80) + ks * 32);
                uint32_t b0[2] = { bb[0], bb[1] };
                uint32_t b1[2] = { bb[2], bb[3] };
                mma_f16(sfr[ntp * 2],     qfr[ks], b0);
                mma_f16(sfr[ntp * 2 + 1], qfr[ks], b1);
            }
        }
    }

    __syncthreads();   // all warps done reading Qs/Ks -> pool reusable as Ps

    // ---- softmax, mask, P -> smem fp16 (aliased region) ----
    const float scale = 0.17677669529663687f;
    const int i0 = w * 16 + g;
    const int i1 = i0 + 8;
    const int myside = w >> 1;
    float sum0 = 0.0f, sum1 = 0.0f;
#pragma unroll
    for (int nt = 0; nt < 8; nt++) {
        int j0 = nt * 8 + 2 * tg;
        float e00, e01, e10, e11;
        if (lastw && ((nt >> 2) != myside)) {
            e00 = e01 = e10 = e11 = 0.0f;
        } else {
            e00 = __expf(sfr[nt][0] * scale + rels[i0 - j0 + 63]);
            e01 = __expf(sfr[nt][1] * scale + rels[i0 - j0 + 62]);
            e10 = __expf(sfr[nt][2] * scale + rels[i1 - j0 + 63]);
            e11 = __expf(sfr[nt][3] * scale + rels[i1 - j0 + 62]);
        }
        sum0 += e00 + e01;
        sum1 += e10 + e11;
        *(uint32_t*)&Ps[i0][j0] = h2u(__floats2half2_rn(e00, e01));
        *(uint32_t*)&Ps[i1][j0] = h2u(__floats2half2_rn(e10, e11));
    }
    sum0 += __shfl_xor_sync(0xffffffffu, sum0, 1);
    sum0 += __shfl_xor_sync(0xffffffffu, sum0, 2);
    sum1 += __shfl_xor_sync(0xffffffffu, sum1, 1);
    sum1 += __shfl_xor_sync(0xffffffffu, sum1, 2);
    if (tg == 0) { sinv[i0] = 1.0f / sum0; sinv[i1] = 1.0f / sum1; }
    __syncwarp();

    // ---- O^T = V^T x P^T  (A via ldsm.trans on row-major V) ----
    float ofr[2][2][4];
#pragma unroll
    for (int mt = 0; mt < 2; mt++)
#pragma unroll
        for (int nt = 0; nt < 2; nt++)
#pragma unroll
            for (int r = 0; r < 4; r++) ofr[mt][nt][r] = 0.0f;
    {
        uint32_t va = smem_u32(&Vs[((lane >> 4) << 3) + (lane & 7)]
                                  [((lane >> 3) & 1) * 8]);
        uint32_t pb = smem_u32(&Ps[w * 16 + ((lane >> 4) << 3) + (lane & 7)]
                                  [((lane >> 3) & 1) * 8]);
#pragma unroll
        for (int ks = 0; ks < 4; ks++) {
            uint32_t a0[4], a1[4], bb[4];
            ldsm_x4_trans(a0, va + (uint32_t)(ks * 16 * 80));        // d0..15
            ldsm_x4_trans(a1, va + (uint32_t)(ks * 16 * 80) + 32);   // d16..31
            ldsm_x4(bb, pb + ks * 32);
            uint32_t b0[2] = { bb[0], bb[1] };
            uint32_t b1[2] = { bb[2], bb[3] };
            mma_f16(ofr[0][0], a0, b0);
            mma_f16(ofr[0][1], a0, b1);
            mma_f16(ofr[1][0], a1, b0);
            mma_f16(ofr[1][1], a1, b1);
        }
    }

    // ---- transpose via aliased fp32 staging (own rows only), normalize ----
#pragma unroll
    for (int mt = 0; mt < 2; mt++)
#pragma unroll
        for (int nt = 0; nt < 2; nt++) {
            int d = mt * 16 + g;
            int i = w * 16 + nt * 8 + 2 * tg;
            Os[i][d]         = ofr[mt][nt][0];
            Os[i + 1][d]     = ofr[mt][nt][1];
            Os[i][d + 8]     = ofr[mt][nt][2];
            Os[i + 1][d + 8] = ofr[mt][nt][3];
        }
    __syncthreads();

#pragma unroll
    for (int it = 0; it < 2; it++) {
        int idx = tid + it * 128;
        int i = idx >> 2, d8 = (idx & 3) * 8;
        float inv = sinv[i];
        float4 v0 = *(float4*)&Os[i][d8];
        float4 v1 = *(float4*)&Os[i][d8 + 4];
        uint4 o;
        o.x = h2u(__floats2half2_rn(v0.x * inv, v0.y * inv));
        o.y = h2u(__floats2half2_rn(v0.z * inv, v0.w * inv));
        o.z = h2u(__floats2half2_rn(v1.x * inv, v1.y * inv));
        o.w = h2u(__floats2half2_rn(v1.z * inv, v1.w * inv));
        *(uint4*)(att + (size_t)(mbase + i) * CDIM + h * HDIM + d8) = o;
    }
}

// ---------------------------------------------------------------------------
extern "C" void kernel_launch(void* const* d_in, const int* in_sizes, int n_in,
                              void* d_out, int out_size)
{
    const float* x       = (const float*)d_in[0];
    const float* w_qkv   = (const float*)d_in[1];
    const float* b_qkv   = (const float*)d_in[2];
    const float* rel_pos = (const float*)d_in[3];
    const float* w_out   = (const float*)d_in[4];
    const float* b_out   = (const float*)d_in[5];
    float* out = (float*)d_out;

    __half *qkvp, *attp, *xhp, *wqkvp, *woutp;
    cudaGetSymbolAddress((void**)&qkvp,  g_qkv);
    cudaGetSymbolAddress((void**)&attp,  g_att);
    cudaGetSymbolAddress((void**)&xhp,   g_xh);
    cudaGetSymbolAddress((void**)&wqkvp, g_wqkvh);
    cudaGetSymbolAddress((void**)&woutp, g_wouth);

    cudaFuncSetAttribute(gemm_f16_kernel<false, __half>,
                         cudaFuncAttributeMaxDynamicSharedMemorySize, GSMEM);
    cudaFuncSetAttribute(gemm_f16_kernel<true, float>,
                         cudaFuncAttributeMaxDynamicSharedMemorySize, GSMEM);

    // K0: fused fp16 pre-conversion (roll folded into x copy), one launch
    {
        int grid = (XN4 + WQ4 + WO4) / 256;   // 33024
        cvt_all_kernel<<<grid, 256>>>(x, w_qkv, w_out, xhp, wqkvp, woutp);
    }
    // K1: QKV projection (fp16 out)
    {
        dim3 grid(QKV_N / 128, MTOT / 128);   // (6, 1024)
        gemm_f16_kernel<false, __half><<<grid, 256, GSMEM>>>(xhp, wqkvp, b_qkv, qkvp, QKV_N);
    }
    // K2: windowed attention (fp16 tensor cores)
    {
        dim3 grid(NWIN, NHEADS);
        attn_f16_kernel<<<grid, 128>>>(qkvp, rel_pos, attp);
    }
    // K3: output projection (fp32 out, roll on write)
    {
        dim3 grid(CDIM / 128, MTOT / 128);    // (2, 1024)
        gemm_f16_kernel<true, float><<<grid, 256, GSMEM>>>(attp, woutp, b_out, out, CDIM);
    }
}

// round 17
// speedup vs baseline: 1.5560x; 1.0059x over previous
#include <cuda_runtime.h>
#include <cuda_fp16.h>
#include <cstdint>

// ---------------------------------------------------------------------------
// Shifted-window MSA. B=8, NSEQ=16384, C=256, P=64, SHIFT=32, NH=8, HD=32.
//   K0: fused cvt: x(rolled)->fp16, w_qkv->fp16, w_out->fp16 (ONE launch)
//   K1: QKV GEMM (fp16 mma, 128x128, cp.async 2-stage)  -> g_qkv (fp16)
//   K2: attention (fp16 mma; split-S register diet; ~16KB smem, 7 blk/SM)
//   K3: out GEMM (same, roll on write)                  -> d_out (fp32)
// tcgen05 unusable: harness ptxas targets sm_103 (no 'a' features).
// GEMM identical to R10/R14/R15 (best measured: K1=199us, K3=66us).
// ---------------------------------------------------------------------------

#define BATCH   8
#define NSEQ    16384
#define CDIM    256
#define PWIN    64
#define SHIFT   32
#define NHEADS  8
#define HDIM    32
#define MTOT    (BATCH * NSEQ)
#define QKV_N   768
#define NWIN    (MTOT / PWIN)
#define WPB     (NSEQ / PWIN)

__device__ __half g_qkv [(size_t)MTOT * QKV_N];
__device__ __half g_att [(size_t)MTOT * CDIM];
__device__ __half g_xh  [(size_t)MTOT * CDIM];
__device__ __half g_wqkvh[(size_t)QKV_N * CDIM];
__device__ __half g_wouth[(size_t)CDIM * CDIM];

// ---------------------------------------------------------------------------
__device__ __forceinline__ uint32_t smem_u32(const void* p) {
    return (uint32_t)__cvta_generic_to_shared(p);
}
__device__ __forceinline__ void mma_f16(float (&d)[4],
                                        const uint32_t (&a)[4],
                                        const uint32_t (&b)[2]) {
    asm volatile(
        "mma.sync.aligned.m16n8k16.row.col.f32.f16.f16.f32 "
        "{%0,%1,%2,%3}, {%4,%5,%6,%7}, {%8,%9}, {%0,%1,%2,%3};"
        : "+f"(d[0]), "+f"(d[1]), "+f"(d[2]), "+f"(d[3])
        : "r"(a[0]), "r"(a[1]), "r"(a[2]), "r"(a[3]), "r"(b[0]), "r"(b[1]));
}
__device__ __forceinline__ void ldsm_x4(uint32_t (&r)[4], uint32_t addr) {
    asm volatile("ldmatrix.sync.aligned.m8n8.x4.shared.b16 {%0,%1,%2,%3}, [%4];"
        : "=r"(r[0]), "=r"(r[1]), "=r"(r[2]), "=r"(r[3]) : "r"(addr));
}
__device__ __forceinline__ void ldsm_x4_trans(uint32_t (&r)[4], uint32_t addr) {
    asm volatile("ldmatrix.sync.aligned.m8n8.x4.trans.shared.b16 {%0,%1,%2,%3}, [%4];"
        : "=r"(r[0]), "=r"(r[1]), "=r"(r[2]), "=r"(r[3]) : "r"(addr));
}
__device__ __forceinline__ uint32_t h2u(__half2 h) {
    return *reinterpret_cast<uint32_t*>(&h);
}
__device__ __forceinline__ void cp_async16(uint32_t dst, const void* src) {
    asm volatile("cp.async.cg.shared.global [%0], [%1], 16;"
                 :: "r"(dst), "l"(src));
}
#define CP_COMMIT() asm volatile("cp.async.commit_group;" ::: "memory")
#define CP_WAIT(n)  asm volatile("cp.async.wait_group %0;" :: "n"(n) : "memory")

// ---------------------------------------------------------------------------
// FP16 GEMM — identical to R10/R14/R15 (best measured config).
// ---------------------------------------------------------------------------
#define HBK 64
#define NKT (CDIM / HBK)            // 4
#define ROWB 144                    // row stride bytes
#define STG_B (2 * 128 * ROWB)      // stage stride = 36864 B
#define BOFF (128 * ROWB)           // B matrix offset within stage = 18432 B
#define GSMEM (2 * STG_B)           // 73728 B

template<bool ROLL_OUT, typename OutT>
__global__ void __launch_bounds__(256, 2)
gemm_f16_kernel(const __half* __restrict__ A,
                const __half* __restrict__ W,
                const float* __restrict__ bias,
                OutT* __restrict__ Cout,
                int Ncols)
{
    extern __shared__ __half smem[];
    const uint32_t sbase = smem_u32(smem);

    const int bm = blockIdx.y * 128;
    const int bn = blockIdx.x * 128;

    const int t    = threadIdx.x;
    const int warp = t >> 5;
    const int lane = t & 31;
    const int g    = lane >> 2;
    const int tg   = lane & 3;

    const int wm = (warp & 1) * 64;
    const int wn = (warp >> 1) * 32;

    int arow[4], ac[4];
#pragma unroll
    for (int i = 0; i < 4; i++) {
        int id = t + i * 256;
        arow[i] = id >> 3;
        ac[i]   = id & 7;
    }
    const __half* Ab = A + (size_t)bm * CDIM;
    const __half* Wb = W + (size_t)bn * CDIM;

    uint32_t dstA[4];
#pragma unroll
    for (int i = 0; i < 4; i++)
        dstA[i] = sbase + (uint32_t)(arow[i] * ROWB + ac[i] * 16);

    uint32_t aAddr[4], bAddr[2];
#pragma unroll
    for (int mt = 0; mt < 4; mt++)
        aAddr[mt] = sbase + (uint32_t)((wm + mt * 16 + (lane & 15)) * ROWB
                                       + (lane >> 4) * 16);
#pragma unroll
    for (int ntp = 0; ntp < 2; ntp++)
        bAddr[ntp] = sbase + BOFF
                   + (uint32_t)((wn + ntp * 16 + ((lane >> 4) << 3) + (lane & 7)) * ROWB
                                + ((lane >> 3) & 1) * 16);

    float acc[4][4][4];
#pragma unroll
    for (int mt = 0; mt < 4; mt++)
#pragma unroll
        for (int nt = 0; nt < 4; nt++)
#pragma unroll
            for (int r = 0; r < 4; r++) acc[mt][nt][r] = 0.0f;

#pragma unroll
    for (int i = 0; i < 4; i++) {
        cp_async16(dstA[i],        Ab + (size_t)arow[i] * CDIM + ac[i] * 8);
        cp_async16(dstA[i] + BOFF, Wb + (size_t)arow[i] * CDIM + ac[i] * 8);
    }
    CP_COMMIT();
#pragma unroll
    for (int i = 0; i < 4; i++) {
        cp_async16(dstA[i] + STG_B,        Ab + (size_t)arow[i] * CDIM + HBK + ac[i] * 8);
        cp_async16(dstA[i] + STG_B + BOFF, Wb + (size_t)arow[i] * CDIM + HBK + ac[i] * 8);
    }
    CP_COMMIT();

#pragma unroll 1
    for (int kt = 0; kt < NKT; kt++) {
        if (kt < NKT - 1) CP_WAIT(1);
        else              CP_WAIT(0);
        __syncthreads();

        const uint32_t so = (kt & 1) ? (uint32_t)STG_B : 0u;
#pragma unroll
        for (int ks = 0; ks < 4; ks++) {
            const uint32_t koff = ks * 32;
            uint32_t afr[4][4], bp[2][4];
#pragma unroll
            for (int mt = 0; mt < 4; mt++) ldsm_x4(afr[mt], aAddr[mt] + so + koff);
#pragma unroll
            for (int ntp = 0; ntp < 2; ntp++) ldsm_x4(bp[ntp], bAddr[ntp] + so + koff);
#pragma unroll
            for (int mt = 0; mt < 4; mt++)
#pragma unroll
                for (int nt = 0; nt < 4; nt++) {
                    uint32_t bfr[2] = { bp[nt >> 1][(nt & 1) * 2],
                                        bp[nt >> 1][(nt & 1) * 2 + 1] };
                    mma_f16(acc[mt][nt], afr[mt], bfr);
                }
        }

        if (kt + 2 < NKT) {
            __syncthreads();
            const int k0 = (kt + 2) * HBK;
#pragma unroll
            for (int i = 0; i < 4; i++) {
                cp_async16(dstA[i] + so,        Ab + (size_t)arow[i] * CDIM + k0 + ac[i] * 8);
                cp_async16(dstA[i] + so + BOFF, Wb + (size_t)arow[i] * CDIM + k0 + ac[i] * 8);
            }
            CP_COMMIT();
        }
    }

#pragma unroll
    for (int mt = 0; mt < 4; mt++) {
        int m0 = bm + wm + mt * 16 + g;
        int m1 = m0 + 8;
        int bi0 = m0 >> 14, t0 = m0 & 16383;
        int bi1 = m1 >> 14, t1 = m1 & 16383;
        int d0 = ROLL_OUT ? ((t0 + SHIFT) & 16383) : t0;
        int d1 = ROLL_OUT ? ((t1 + SHIFT) & 16383) : t1;
        OutT* row0 = Cout + (size_t)((bi0 << 14) + d0) * Ncols;
        OutT* row1 = Cout + (size_t)((bi1 << 14) + d1) * Ncols;
#pragma unroll
        for (int nt = 0; nt < 4; nt++) {
            int col = bn + wn + nt * 8 + 2 * tg;
            float b0 = bias[col], b1 = bias[col + 1];
            if constexpr (sizeof(OutT) == 4) {
                *(float2*)((float*)row0 + col) =
                    make_float2(acc[mt][nt][0] + b0, acc[mt][nt][1] + b1);
                *(float2*)((float*)row1 + col) =
                    make_float2(acc[mt][nt][2] + b0, acc[mt][nt][3] + b1);
            } else {
                *(uint32_t*)((__half*)row0 + col) =
                    h2u(__floats2half2_rn(acc[mt][nt][0] + b0, acc[mt][nt][1] + b1));
                *(uint32_t*)((__half*)row1 + col) =
                    h2u(__floats2half2_rn(acc[mt][nt][2] + b0, acc[mt][nt][3] + b1));
            }
        }
    }
}

// ---------------------------------------------------------------------------
// Fused cvt pre-pass (ONE launch) — identical to R14/R15.
// ---------------------------------------------------------------------------
#define XN4  (MTOT * CDIM / 4)          // 8388608
#define WQ4  (QKV_N * CDIM / 4)         // 49152
#define WO4  (CDIM * CDIM / 4)          // 16384

__global__ void cvt_all_kernel(const float* __restrict__ x,
                               const float* __restrict__ w_qkv,
                               const float* __restrict__ w_out,
                               __half* __restrict__ xh,
                               __half* __restrict__ wqkvh,
                               __half* __restrict__ wouth)
{
    size_t i4 = (size_t)blockIdx.x * 256 + threadIdx.x;
    if (i4 < (size_t)XN4) {
        size_t fi = i4 * 4;
        int m = (int)(fi >> 8);
        int c = (int)(fi & 255);
        int bi = m >> 14, t = m & 16383;
        int s = (t + SHIFT) & 16383;
        float4 v = *(const float4*)(x + (size_t)((bi << 14) + s) * CDIM + c);
        *(uint2*)(xh + fi) = make_uint2(h2u(__floats2half2_rn(v.x, v.y)),
                                        h2u(__floats2half2_rn(v.z, v.w)));
    } else if (i4 < (size_t)(XN4 + WQ4)) {
        size_t j = i4 - XN4;
        float4 v = *(const float4*)(w_qkv + j * 4);
        *(uint2*)(wqkvh + j * 4) = make_uint2(h2u(__floats2half2_rn(v.x, v.y)),
                                              h2u(__floats2half2_rn(v.z, v.w)));
    } else {
        size_t j = i4 - XN4 - WQ4;
        float4 v = *(const float4*)(w_out + j * 4);
        *(uint2*)(wouth + j * 4) = make_uint2(h2u(__floats2half2_rn(v.x, v.y)),
                                              h2u(__floats2half2_rn(v.z, v.w)));
    }
}

// ---------------------------------------------------------------------------
// FP16 tensor-core attention (v3): as R15 (ldsm.trans V, Ps aliased on Qs/Ks)
// plus SPLIT-S register diet: S tiles processed in two n-halves so only 16
// sfr registers are live at once -> ~72-80 regs -> 6-7 blocks/SM (was ~5).
// Sum accumulation order over nt is unchanged -> bit-identical output.
// ---------------------------------------------------------------------------
__global__ void __launch_bounds__(128, 6)
attn_f16_kernel(const __half* __restrict__ qkv,
                const float* __restrict__ rel_pos,
                __half* __restrict__ att)
{
    __shared__ __align__(16) __half QKpool[2 * 64 * 40];  // 10240 B
    __shared__ __align__(16) __half Vs[64][40];           // 5120 B
    __shared__ float  rels[128];
    __shared__ float  sinv[64];

    __half (*Qs)[40] = reinterpret_cast<__half (*)[40]>(QKpool);
    __half (*Ks)[40] = reinterpret_cast<__half (*)[40]>(QKpool + 64 * 40);
    __half (*Ps)[72] = reinterpret_cast<__half (*)[72]>(QKpool);  // 9216 B alias
    float  (*Os)[36] = reinterpret_cast<float (*)[36]>(QKpool);   // alias of Ps

    const int wi = blockIdx.x;
    const int h  = blockIdx.y;
    const int tid  = threadIdx.x;
    const int w    = tid >> 5;
    const int lane = tid & 31;
    const int g    = lane >> 2;
    const int tg   = lane & 3;
    const int mbase = wi * PWIN;
    const bool lastw = ((wi & (WPB - 1)) == (WPB - 1));

    // ---- stage Q, K, V (row-major [j][d], uint4 per thread) ----
#pragma unroll
    for (int it = 0; it < 2; it++) {
        int idx = tid + it * 128;
        int j = idx >> 2, c8 = (idx & 3) * 8;
        const __half* base = qkv + (size_t)(mbase + j) * QKV_N + h * HDIM + c8;
        uint4 q4 = *(const uint4*)(base);
        uint4 k4 = *(const uint4*)(base + 256);
        uint4 v4 = *(const uint4*)(base + 512);
        *(uint4*)&Qs[j][c8] = q4;
        *(uint4*)&Ks[j][c8] = k4;
        *(uint4*)&Vs[j][c8] = v4;
    }
    if (tid < 127) rels[tid] = rel_pos[h * 127 + tid];
    __syncthreads();

    // ---- Q fragments (regs; Qs dead afterwards) ----
    uint32_t qfr[2][4];
    {
        uint32_t qa = smem_u32(&Qs[w * 16 + (lane & 15)][(lane >> 4) * 8]);
        ldsm_x4(qfr[0], qa);
        ldsm_x4(qfr[1], qa + 32);
    }

    // ---- S = Q K^T in two n-halves; exp into registers, defer Ps stores ----
    const float scale = 0.17677669529663687f;
    const int i0 = w * 16 + g;
    const int i1 = i0 + 8;
    const int myside = w >> 1;
    float sum0 = 0.0f, sum1 = 0.0f;
    // exp results held packed (fp16x2) until the pool is safe to overwrite
    uint32_t pfr[8][2];

    const uint32_t kb = smem_u32(&Ks[((lane >> 4) << 3) + (lane & 7)]
                                    [((lane >> 3) & 1) * 8]);
#pragma unroll
    for (int hf = 0; hf < 2; hf++) {
        float sfr[4][4];
#pragma unroll
        for (int j = 0; j < 4; j++)
#pragma unroll
            for (int r = 0; r < 4; r++) sfr[j][r] = 0.0f;

#pragma unroll
        for (int ks = 0; ks < 2; ks++) {
#pragma unroll
            for (int p = 0; p < 2; p++) {           // ntp = hf*2 + p
                uint32_t bb[4];
                ldsm_x4(bb, kb + (uint32_t)((hf * 2 + p) * 16 * 80) + ks * 32);
                uint32_t b0[2] = { bb[0], bb[1] };
                uint32_t b1[2] = { bb[2], bb[3] };
                mma_f16(sfr[p * 2],     qfr[ks], b0);
                mma_f16(sfr[p * 2 + 1], qfr[ks], b1);
            }
        }

        const bool blocked = lastw && (hf != myside);
#pragma unroll
        for (int j = 0; j < 4; j++) {
            int nt = hf * 4 + j;
            int j0 = nt * 8 + 2 * tg;
            float e00, e01, e10, e11;
            if (blocked) {
                e00 = e01 = e10 = e11 = 0.0f;
            } else {
                e00 = __expf(sfr[j][0] * scale + rels[i0 - j0 + 63]);
                e01 = __expf(sfr[j][1] * scale + rels[i0 - j0 + 62]);
                e10 = __expf(sfr[j][2] * scale + rels[i1 - j0 + 63]);
                e11 = __expf(sfr[j][3] * scale + rels[i1 - j0 + 62]);
            }
            sum0 += e00 + e01;
            sum1 += e10 + e11;
            pfr[nt][0] = h2u(__floats2half2_rn(e00, e01));
            pfr[nt][1] = h2u(__floats2half2_rn(e10, e11));
        }
    }

    __syncthreads();   // all warps done reading Qs/Ks -> pool reusable as Ps

#pragma unroll
    for (int nt = 0; nt < 8; nt++) {
        int j0 = nt * 8 + 2 * tg;
        *(uint32_t*)&Ps[i0][j0] = pfr[nt][0];
        *(uint32_t*)&Ps[i1][j0] = pfr[nt][1];
    }
    sum0 += __shfl_xor_sync(0xffffffffu, sum0, 1);
    sum0 += __shfl_xor_sync(0xffffffffu, sum0, 2);
    sum1 += __shfl_xor_sync(0xffffffffu, sum1, 1);
    sum1 += __shfl_xor_sync(0xffffffffu, sum1, 2);
    if (tg == 0) { sinv[i0] = 1.0f / sum0; sinv[i1] = 1.0f / sum1; }
    __syncwarp();

    // ---- O^T = V^T x P^T  (A via ldsm.trans on row-major V) ----
    float ofr[2][2][4];
#pragma unroll
    for (int mt = 0; mt < 2; mt++)
#pragma unroll
        for (int nt = 0; nt < 2; nt++)
#pragma unroll
            for (int r = 0; r < 4; r++) ofr[mt][nt][r] = 0.0f;
    {
        uint32_t va = smem_u32(&Vs[((lane >> 4) << 3) + (lane & 7)]
                                  [((lane >> 3) & 1) * 8]);
        uint32_t pb = smem_u32(&Ps[w * 16 + ((lane >> 4) << 3) + (lane & 7)]
                                  [((lane >> 3) & 1) * 8]);
#pragma unroll
        for (int ks = 0; ks < 4; ks++) {
            uint32_t a0[4], a1[4], bb[4];
            ldsm_x4_trans(a0, va + (uint32_t)(ks * 16 * 80));        // d0..15
            ldsm_x4_trans(a1, va + (uint32_t)(ks * 16 * 80) + 32);   // d16..31
            ldsm_x4(bb, pb + ks * 32);
            uint32_t b0[2] = { bb[0], bb[1] };
            uint32_t b1[2] = { bb[2], bb[3] };
            mma_f16(ofr[0][0], a0, b0);
            mma_f16(ofr[0][1], a0, b1);
            mma_f16(ofr[1][0], a1, b0);
            mma_f16(ofr[1][1], a1, b1);
        }
    }

    // ---- transpose via aliased fp32 staging (own rows only), normalize ----
#pragma unroll
    for (int mt = 0; mt < 2; mt++)
#pragma unroll
        for (int nt = 0; nt < 2; nt++) {
            int d = mt * 16 + g;
            int i = w * 16 + nt * 8 + 2 * tg;
            Os[i][d]         = ofr[mt][nt][0];
            Os[i + 1][d]     = ofr[mt][nt][1];
            Os[i][d + 8]     = ofr[mt][nt][2];
            Os[i + 1][d + 8] = ofr[mt][nt][3];
        }
    __syncthreads();

#pragma unroll
    for (int it = 0; it < 2; it++) {
        int idx = tid + it * 128;
        int i = idx >> 2, d8 = (idx & 3) * 8;
        float inv = sinv[i];
        float4 v0 = *(float4*)&Os[i][d8];
        float4 v1 = *(float4*)&Os[i][d8 + 4];
        uint4 o;
        o.x = h2u(__floats2half2_rn(v0.x * inv, v0.y * inv));
        o.y = h2u(__floats2half2_rn(v0.z * inv, v0.w * inv));
        o.z = h2u(__floats2half2_rn(v1.x * inv, v1.y * inv));
        o.w = h2u(__floats2half2_rn(v1.z * inv, v1.w * inv));
        *(uint4*)(att + (size_t)(mbase + i) * CDIM + h * HDIM + d8) = o;
    }
}

// ---------------------------------------------------------------------------
extern "C" void kernel_launch(void* const* d_in, const int* in_sizes, int n_in,
                              void* d_out, int out_size)
{
    const float* x       = (const float*)d_in[0];
    const float* w_qkv   = (const float*)d_in[1];
    const float* b_qkv   = (const float*)d_in[2];
    const float* rel_pos = (const float*)d_in[3];
    const float* w_out   = (const float*)d_in[4];
    const float* b_out   = (const float*)d_in[5];
    float* out = (float*)d_out;

    __half *qkvp, *attp, *xhp, *wqkvp, *woutp;
    cudaGetSymbolAddress((void**)&qkvp,  g_qkv);
    cudaGetSymbolAddress((void**)&attp,  g_att);
    cudaGetSymbolAddress((void**)&xhp,   g_xh);
    cudaGetSymbolAddress((void**)&wqkvp, g_wqkvh);
    cudaGetSymbolAddress((void**)&woutp, g_wouth);

    cudaFuncSetAttribute(gemm_f16_kernel<false, __half>,
                         cudaFuncAttributeMaxDynamicSharedMemorySize, GSMEM);
    cudaFuncSetAttribute(gemm_f16_kernel<true, float>,
                         cudaFuncAttributeMaxDynamicSharedMemorySize, GSMEM);

    // K0: fused fp16 pre-conversion (roll folded into x copy), one launch
    {
        int grid = (XN4 + WQ4 + WO4) / 256;   // 33024
        cvt_all_kernel<<<grid, 256>>>(x, w_qkv, w_out, xhp, wqkvp, woutp);
    }
    // K1: QKV projection (fp16 out)
    {
        dim3 grid(QKV_N / 128, MTOT / 128);   // (6, 1024)
        gemm_f16_kernel<false, __half><<<grid, 256, GSMEM>>>(xhp, wqkvp, b_qkv, qkvp, QKV_N);
    }
    // K2: windowed attention (fp16 tensor cores)
    {
        dim3 grid(NWIN, NHEADS);
        attn_f16_kernel<<<grid, 128>>>(qkvp, rel_pos, attp);
    }
    // K3: output projection (fp32 out, roll on write)
    {
        dim3 grid(CDIM / 128, MTOT / 128);    // (2, 1024)
        gemm_f16_kernel<true, float><<<grid, 256, GSMEM>>>(attp, woutp, b_out, out, CDIM);
    }
}